// round 12
// baseline (speedup 1.0000x reference)
#include <cuda_runtime.h>
#include <cuda_bf16.h>
#include <cstdint>

#define N_PIX 32768   // B*H*W
#define EMB   64
#define CH    128
#define NCODE 8192
#define HW    1024

// ---------------------------------------------------------------------------
// scratch (no allocations allowed)
// ---------------------------------------------------------------------------
__device__ float         g_ze[N_PIX * EMB];     // queries fp32, 8 MB
__device__ float         g_eps2[N_PIX];         // 2x coarse-error bound per query
__device__ int           g_ind[N_PIX];
__device__ float         g_wn[NCODE];           // 0.5*||w||^2 fp32
__device__ __nv_bfloat16 g_cb[NCODE * EMB];     // codebook bf16 row-major
__device__ int           g_wmaxi = 0;
__device__ float         g_loss;

__device__ __forceinline__ uint32_t smem_u32(const void* p) {
    uint32_t a;
    asm("{ .reg .u64 t; cvta.to.shared.u64 t, %1; cvt.u32.u64 %0, t; }"
        : "=r"(a) : "l"(p));
    return a;
}
__device__ __forceinline__ uint32_t bf2(float lo, float hi) {
    uint32_t r;
    asm("cvt.rn.bf16x2.f32 %0, %1, %2;" : "=r"(r) : "f"(hi), "f"(lo));
    return r;
}
__device__ __forceinline__ void mma_bf16(float* c, const uint32_t* a,
                                         uint32_t b0, uint32_t b1) {
    asm volatile(
        "mma.sync.aligned.m16n8k16.row.col.f32.bf16.bf16.f32 "
        "{%0,%1,%2,%3},{%4,%5,%6,%7},{%8,%9},{%0,%1,%2,%3};"
        : "+f"(c[0]), "+f"(c[1]), "+f"(c[2]), "+f"(c[3])
        : "r"(a[0]), "r"(a[1]), "r"(a[2]), "r"(a[3]), "r"(b0), "r"(b1));
}

// ---------------------------------------------------------------------------
// K0: code half-norms fp32, bf16 codebook, max norm, zero loss
// ---------------------------------------------------------------------------
__global__ void k_wn(const float* __restrict__ ew) {
    int j = blockIdx.x * blockDim.x + threadIdx.x;
    const float4* p = (const float4*)(ew + (size_t)j * EMB);
    uint4 packed[8];
    float s = 0.f;
#pragma unroll
    for (int i = 0; i < 8; ++i) {
        float4 a = p[2 * i], b = p[2 * i + 1];
        s += a.x * a.x + a.y * a.y + a.z * a.z + a.w * a.w;
        s += b.x * b.x + b.y * b.y + b.z * b.z + b.w * b.w;
        packed[i] = make_uint4(bf2(a.x, a.y), bf2(a.z, a.w),
                               bf2(b.x, b.y), bf2(b.z, b.w));
    }
    uint4* dst = (uint4*)(g_cb + (size_t)j * EMB);
#pragma unroll
    for (int i = 0; i < 8; ++i) dst[i] = packed[i];
    g_wn[j] = 0.5f * s;
    atomicMax(&g_wmaxi, __float_as_int(sqrtf(s)));
    if (j == 0) g_loss = 0.f;
}

// ---------------------------------------------------------------------------
// K1: projection -> g_ze fp32
// ---------------------------------------------------------------------------
__global__ __launch_bounds__(256) void k_proj(const float* __restrict__ z,
                                              const float* __restrict__ pw,
                                              const float* __restrict__ pb) {
    __shared__ float projs[EMB][CH + 4];
    __shared__ float zs[CH][18];
    int tid = threadIdx.x;
    int pbase = blockIdx.x * 16;
    for (int i = tid; i < EMB * CH / 4; i += 256) {
        int e = i >> 5;
        int c4 = (i & 31) << 2;
        float4 v = ((const float4*)pw)[i];
        projs[e][c4] = v.x; projs[e][c4 + 1] = v.y;
        projs[e][c4 + 2] = v.z; projs[e][c4 + 3] = v.w;
    }
    for (int i = tid; i < CH * 16; i += 256) {
        int c = i >> 4, p = i & 15, n = pbase + p;
        zs[c][p] = z[(n >> 10) * (CH * HW) + c * HW + (n & 1023)];
    }
    __syncthreads();
    int e = tid & 63, pg = tid >> 6;
    float bias = pb[e];
    for (int p = pg; p < 16; p += 4) {
        float acc = bias;
#pragma unroll
        for (int c = 0; c < CH; c += 4) {
            float4 w = *(const float4*)&projs[e][c];
            acc += w.x * zs[c][p];     acc += w.y * zs[c + 1][p];
            acc += w.z * zs[c + 2][p]; acc += w.w * zs[c + 3][p];
        }
        g_ze[(pbase + p) * EMB + e] = acc;
    }
}

// ---------------------------------------------------------------------------
// K1b: per-query eps2 = ||x|| * wmax / 64 + slack  (>=2x bf16 dot error bound)
// ---------------------------------------------------------------------------
__global__ __launch_bounds__(256) void k_xn() {
    int n = blockIdx.x * blockDim.x + threadIdx.x;
    const float4* p = (const float4*)(g_ze + (size_t)n * EMB);
    float s = 0.f;
#pragma unroll
    for (int i = 0; i < 16; ++i) {
        float4 v = p[i];
        s += v.x * v.x + v.y * v.y + v.z * v.z + v.w * v.w;
    }
    float wmax = __int_as_float(g_wmaxi);
    g_eps2[n] = sqrtf(s) * wmax * (1.0f / 64.0f) + 0.02f;
}

// ---------------------------------------------------------------------------
// K2: mma.sync bf16 coarse argmax + exact fp32 rescue
// 256 threads; tile 128q x 128c; K=64 in regs (A), B double-buffered cp.async.
// ---------------------------------------------------------------------------
#define NT  64             // 8192 / 128 code tiles
#define CAP 48
#define SM_B   0u          // 2 x 16384
#define SM_WN  32768u      // 8192 f32
#define SM_CV  65536u      // 128*CAP f32
#define SM_CI  90112u      // 128*CAP i32
#define SM_CNT 114688u     // 128 i32
#define SMEM_TOTAL 115200

__device__ __forceinline__ float exact_score(const float* __restrict__ qv,
                                             const float* __restrict__ ew, int idx) {
    const float4* w = (const float4*)(ew + (size_t)idx * EMB);
    float s = 0.f;
#pragma unroll
    for (int i = 0; i < 16; ++i) {
        float4 v = w[i];
        s = fmaf(qv[4 * i], v.x, s);
        s = fmaf(qv[4 * i + 1], v.y, s);
        s = fmaf(qv[4 * i + 2], v.z, s);
        s = fmaf(qv[4 * i + 3], v.w, s);
    }
    return s - __ldg(&g_wn[idx]);
}

__device__ __forceinline__ void load_btile(uint32_t dstbase, const char* srcbase,
                                           int tid) {
#pragma unroll
    for (int r = 0; r < 4; ++r) {
        int i = tid + 256 * r;          // chunk id 0..1023
        int n = i >> 3, c = i & 7;      // code row, 16B chunk
        uint32_t dst = dstbase + n * 128 + (((uint32_t)(c ^ (n & 7))) << 4);
        const char* src = srcbase + n * 128 + c * 16;
        asm volatile("cp.async.cg.shared.global [%0], [%1], 16;"
                     :: "r"(dst), "l"(src) : "memory");
    }
    asm volatile("cp.async.commit_group;" ::: "memory");
}

__global__ __launch_bounds__(256, 1) void k_argmax_mma(const float* __restrict__ ew) {
    extern __shared__ char smc[];
    float* wns  = (float*)(smc + SM_WN);
    float* cval = (float*)(smc + SM_CV);
    int*   cidx = (int*)(smc + SM_CI);
    int*   cnt  = (int*)(smc + SM_CNT);
    uint32_t sb = smem_u32(smc);

    int tid = threadIdx.x;
    int wid = tid >> 5, lane = tid & 31;
    int warpm = wid & 3, warpn = wid >> 2;
    int g = lane >> 2, tq = lane & 3;
    int qb = blockIdx.x * 128;

    if (tid < 128) cnt[tid] = 0;
    for (int i = tid; i < NCODE / 4; i += 256)
        ((float4*)wns)[i] = ((const float4*)g_wn)[i];

    // A fragments: built once from g_ze (fp32 -> bf16x2)
    uint32_t afr[2][4][4];
#pragma unroll
    for (int mt = 0; mt < 2; ++mt) {
        const float* r0 = g_ze + (size_t)(qb + warpm * 32 + mt * 16 + g) * EMB;
        const float* r1 = r0 + 8 * EMB;
#pragma unroll
        for (int ks = 0; ks < 4; ++ks) {
            float2 v;
            v = *(const float2*)(r0 + ks * 16 + 2 * tq);     afr[mt][ks][0] = bf2(v.x, v.y);
            v = *(const float2*)(r1 + ks * 16 + 2 * tq);     afr[mt][ks][1] = bf2(v.x, v.y);
            v = *(const float2*)(r0 + ks * 16 + 2 * tq + 8); afr[mt][ks][2] = bf2(v.x, v.y);
            v = *(const float2*)(r1 + ks * 16 + 2 * tq + 8); afr[mt][ks][3] = bf2(v.x, v.y);
        }
    }

    float eps2v[2][2], thr[2][2];
#pragma unroll
    for (int mt = 0; mt < 2; ++mt)
#pragma unroll
        for (int h = 0; h < 2; ++h) {
            eps2v[mt][h] = __ldg(&g_eps2[qb + warpm * 32 + mt * 16 + g + 8 * h]);
            thr[mt][h] = -3.0e38f;
        }

    int laneRow = lane & 7, laneTile = (lane >> 3) & 1;
    uint32_t rowoff = (uint32_t)laneRow * 128u;
    uint32_t cks[4];
#pragma unroll
    for (int ks = 0; ks < 4; ++ks)
        cks[ks] = ((uint32_t)((ks * 2 + laneTile) ^ laneRow)) << 4;

    // prologue: tile 0
    load_btile(sb + SM_B, (const char*)g_cb, tid);

    for (int t = 0; t < NT; ++t) {
        if (t + 1 < NT) {
            load_btile(sb + SM_B + (uint32_t)((t + 1) & 1) * 16384u,
                       (const char*)g_cb + (size_t)(t + 1) * 16384, tid);
            asm volatile("cp.async.wait_group 1;" ::: "memory");
        } else {
            asm volatile("cp.async.wait_group 0;" ::: "memory");
        }
        __syncthreads();

        float acc[2][8][4];
#pragma unroll
        for (int mt = 0; mt < 2; ++mt)
#pragma unroll
            for (int j = 0; j < 8; ++j)
#pragma unroll
                for (int k = 0; k < 4; ++k) acc[mt][j][k] = 0.f;

        uint32_t bbase = sb + SM_B + (uint32_t)(t & 1) * 16384u + rowoff
                       + (uint32_t)warpn * 8192u;   // warpn picks codes 0-63 / 64-127
#pragma unroll
        for (int j = 0; j < 8; ++j) {
#pragma unroll
            for (int ks = 0; ks < 4; ++ks) {
                uint32_t b0, b1;
                asm volatile("ldmatrix.sync.aligned.m8n8.x2.shared.b16 {%0,%1}, [%2];"
                             : "=r"(b0), "=r"(b1)
                             : "r"(bbase + (uint32_t)j * 1024u + cks[ks]));
                mma_bf16(acc[0][j], afr[0][ks], b0, b1);
                mma_bf16(acc[1][j], afr[1][ks], b0, b1);
            }
        }

        // scan from accumulators
        int cb0 = t * 128 + warpn * 64;
        int qlb = warpm * 32;
#pragma unroll
        for (int j = 0; j < 8; ++j) {
            // FIX (R9): norm index must include the tile offset t*128
            float2 wn2 = *(const float2*)&wns[t * 128 + warpn * 64 + j * 8 + 2 * tq];
            int col0 = cb0 + j * 8 + 2 * tq;
#pragma unroll
            for (int mt = 0; mt < 2; ++mt) {
                int ql = qlb + mt * 16 + g;
                float s0 = acc[mt][j][0] - wn2.x;
                float s1 = acc[mt][j][1] - wn2.y;
                float s2 = acc[mt][j][2] - wn2.x;
                float s3 = acc[mt][j][3] - wn2.y;
                if (s0 > thr[mt][0]) {
                    int p = atomicAdd(&cnt[ql], 1);
                    if (p < CAP) { cval[ql * CAP + p] = s0; cidx[ql * CAP + p] = col0; }
                    thr[mt][0] = fmaxf(thr[mt][0], s0 - eps2v[mt][0]);
                }
                if (s1 > thr[mt][0]) {
                    int p = atomicAdd(&cnt[ql], 1);
                    if (p < CAP) { cval[ql * CAP + p] = s1; cidx[ql * CAP + p] = col0 + 1; }
                    thr[mt][0] = fmaxf(thr[mt][0], s1 - eps2v[mt][0]);
                }
                if (s2 > thr[mt][1]) {
                    int p = atomicAdd(&cnt[ql + 8], 1);
                    if (p < CAP) { cval[(ql + 8) * CAP + p] = s2; cidx[(ql + 8) * CAP + p] = col0; }
                    thr[mt][1] = fmaxf(thr[mt][1], s2 - eps2v[mt][1]);
                }
                if (s3 > thr[mt][1]) {
                    int p = atomicAdd(&cnt[ql + 8], 1);
                    if (p < CAP) { cval[(ql + 8) * CAP + p] = s3; cidx[(ql + 8) * CAP + p] = col0 + 1; }
                    thr[mt][1] = fmaxf(thr[mt][1], s3 - eps2v[mt][1]);
                }
            }
        }
        // share threshold within each 4-lane quad (same query rows)
#pragma unroll
        for (int mt = 0; mt < 2; ++mt)
#pragma unroll
            for (int h = 0; h < 2; ++h) {
                float v = thr[mt][h];
                v = fmaxf(v, __shfl_xor_sync(0xffffffffu, v, 1));
                v = fmaxf(v, __shfl_xor_sync(0xffffffffu, v, 2));
                thr[mt][h] = v;
            }
        __syncthreads();
    }

    // final: filter + exact fp32 rescore (order-independent -> deterministic)
    if (tid < 128) {
        int q = tid, n = qb + q;
        int c = cnt[q];
        float qv[64];
        const float4* qp = (const float4*)(g_ze + (size_t)n * EMB);
#pragma unroll
        for (int i = 0; i < 16; ++i) {
            float4 v = qp[i];
            qv[4 * i] = v.x; qv[4 * i + 1] = v.y;
            qv[4 * i + 2] = v.z; qv[4 * i + 3] = v.w;
        }
        float bv = -3.0e38f;
        int bi = 0x7fffffff;
        if (c > CAP) {  // overflow fallback: exact full scan (rare)
            for (int id = 0; id < NCODE; ++id) {
                float s = exact_score(qv, ew, id);
                if (s > bv) { bv = s; bi = id; }
            }
        } else {
            float cm = -3.0e38f;
            for (int k = 0; k < c; ++k) cm = fmaxf(cm, cval[q * CAP + k]);
            float th = cm - __ldg(&g_eps2[n]);
            for (int k = 0; k < c; ++k) {
                if (cval[q * CAP + k] >= th) {
                    int id = cidx[q * CAP + k];
                    float s = exact_score(qv, ew, id);
                    if (s > bv || (s == bv && id < bi)) { bv = s; bi = id; }
                }
            }
        }
        g_ind[n] = bi;
    }
}

// ---------------------------------------------------------------------------
// K3: gather + outputs + loss partials
// ---------------------------------------------------------------------------
__global__ __launch_bounds__(256) void k_gather(const float* __restrict__ ew,
                                                float* __restrict__ out,
                                                int full_out) {
    int tid = threadIdx.x;
    int n = blockIdx.x * 4 + (tid >> 6);
    int e = tid & 63;
    int idx = g_ind[n];
    float v = ew[idx * EMB + e];
    float d = v - g_ze[n * EMB + e];
    int b = n >> 10;
    int hw = n & 1023;
    out[b * (EMB * HW) + e * HW + hw] = v;
    if (full_out) {
        out[N_PIX * EMB + n * EMB + e] = v;
        if (e == 0) out[2 * N_PIX * EMB + 1 + n] = (float)idx;
    }
    float s = d * d;
#pragma unroll
    for (int off = 16; off > 0; off >>= 1)
        s += __shfl_down_sync(0xffffffffu, s, off);
    __shared__ float ps[8];
    if ((tid & 31) == 0) ps[tid >> 5] = s;
    __syncthreads();
    if (tid < 8) {
        s = ps[tid];
#pragma unroll
        for (int off = 4; off > 0; off >>= 1)
            s += __shfl_down_sync(0xffu, s, off);
        if (tid == 0) atomicAdd(&g_loss, s);
    }
}

__global__ void k_fin(float* __restrict__ out, int full_out) {
    if (full_out)
        out[2 * N_PIX * EMB] = 12.5f * g_loss / (float)(N_PIX * EMB);
}

// ---------------------------------------------------------------------------
extern "C" void kernel_launch(void* const* d_in, const int* in_sizes, int n_in,
                              void* d_out, int out_size) {
    const float* z  = (const float*)d_in[0];
    const float* pw = (const float*)d_in[1];
    const float* pb = (const float*)d_in[2];
    const float* ew = (const float*)d_in[3];
    float* out = (float*)d_out;

    int full_out = (out_size >= 2 * N_PIX * EMB + 1 + N_PIX) ? 1 : 0;

    cudaFuncSetAttribute(k_argmax_mma, cudaFuncAttributeMaxDynamicSharedMemorySize,
                         SMEM_TOTAL);

    k_wn<<<NCODE / 256, 256>>>(ew);
    k_proj<<<N_PIX / 16, 256>>>(z, pw, pb);
    k_xn<<<N_PIX / 256, 256>>>();
    k_argmax_mma<<<N_PIX / 128, 256, SMEM_TOTAL>>>(ew);
    k_gather<<<N_PIX / 4, 256>>>(ew, out, full_out);
    k_fin<<<1, 1>>>(out, full_out);
}

// round 13
// speedup vs baseline: 15.1990x; 15.1990x over previous
#include <cuda_runtime.h>
#include <cuda_bf16.h>
#include <cstdint>

#define N_PIX 32768   // B*H*W
#define EMB   64
#define CH    128
#define NCODE 8192
#define HW    1024

// ---------------------------------------------------------------------------
// scratch (no allocations allowed)
// ---------------------------------------------------------------------------
__device__ float         g_ze[N_PIX * EMB];     // queries fp32, 8 MB
__device__ float         g_eps2[N_PIX];         // >=2x coarse-error bound per query
__device__ int           g_ind[N_PIX];
__device__ float         g_wn[NCODE];           // 0.5*||w||^2 fp32
__device__ __nv_bfloat16 g_cb[NCODE * EMB];     // codebook bf16 row-major
__device__ int           g_wmaxi = 0;
__device__ float         g_loss;

__device__ __forceinline__ uint32_t smem_u32(const void* p) {
    uint32_t a;
    asm("{ .reg .u64 t; cvta.to.shared.u64 t, %1; cvt.u32.u64 %0, t; }"
        : "=r"(a) : "l"(p));
    return a;
}
__device__ __forceinline__ uint32_t bf2(float lo, float hi) {
    uint32_t r;
    asm("cvt.rn.bf16x2.f32 %0, %1, %2;" : "=r"(r) : "f"(hi), "f"(lo));
    return r;
}
__device__ __forceinline__ void mma_bf16(float* c, const uint32_t* a,
                                         uint32_t b0, uint32_t b1) {
    asm volatile(
        "mma.sync.aligned.m16n8k16.row.col.f32.bf16.bf16.f32 "
        "{%0,%1,%2,%3},{%4,%5,%6,%7},{%8,%9},{%0,%1,%2,%3};"
        : "+f"(c[0]), "+f"(c[1]), "+f"(c[2]), "+f"(c[3])
        : "r"(a[0]), "r"(a[1]), "r"(a[2]), "r"(a[3]), "r"(b0), "r"(b1));
}
// ordered-int encoding for float atomicMax on smem
__device__ __forceinline__ uint32_t fenc(float f) {
    uint32_t i = __float_as_uint(f);
    return (i & 0x80000000u) ? ~i : (i | 0x80000000u);
}
__device__ __forceinline__ float fdec(uint32_t u) {
    return (u & 0x80000000u) ? __uint_as_float(u & 0x7fffffffu)
                             : __uint_as_float(~u);
}

// ---------------------------------------------------------------------------
// K0: code half-norms fp32, bf16 codebook, max norm, zero loss
// ---------------------------------------------------------------------------
__global__ void k_wn(const float* __restrict__ ew) {
    int j = blockIdx.x * blockDim.x + threadIdx.x;
    const float4* p = (const float4*)(ew + (size_t)j * EMB);
    uint4 packed[8];
    float s = 0.f;
#pragma unroll
    for (int i = 0; i < 8; ++i) {
        float4 a = p[2 * i], b = p[2 * i + 1];
        s += a.x * a.x + a.y * a.y + a.z * a.z + a.w * a.w;
        s += b.x * b.x + b.y * b.y + b.z * b.z + b.w * b.w;
        packed[i] = make_uint4(bf2(a.x, a.y), bf2(a.z, a.w),
                               bf2(b.x, b.y), bf2(b.z, b.w));
    }
    uint4* dst = (uint4*)(g_cb + (size_t)j * EMB);
#pragma unroll
    for (int i = 0; i < 8; ++i) dst[i] = packed[i];
    g_wn[j] = 0.5f * s;
    atomicMax(&g_wmaxi, __float_as_int(sqrtf(s)));
    if (j == 0) g_loss = 0.f;
}

// ---------------------------------------------------------------------------
// K1: projection -> g_ze fp32
// ---------------------------------------------------------------------------
__global__ __launch_bounds__(256) void k_proj(const float* __restrict__ z,
                                              const float* __restrict__ pw,
                                              const float* __restrict__ pb) {
    __shared__ float projs[EMB][CH + 4];
    __shared__ float zs[CH][18];
    int tid = threadIdx.x;
    int pbase = blockIdx.x * 16;
    for (int i = tid; i < EMB * CH / 4; i += 256) {
        int e = i >> 5;
        int c4 = (i & 31) << 2;
        float4 v = ((const float4*)pw)[i];
        projs[e][c4] = v.x; projs[e][c4 + 1] = v.y;
        projs[e][c4 + 2] = v.z; projs[e][c4 + 3] = v.w;
    }
    for (int i = tid; i < CH * 16; i += 256) {
        int c = i >> 4, p = i & 15, n = pbase + p;
        zs[c][p] = z[(n >> 10) * (CH * HW) + c * HW + (n & 1023)];
    }
    __syncthreads();
    int e = tid & 63, pg = tid >> 6;
    float bias = pb[e];
    for (int p = pg; p < 16; p += 4) {
        float acc = bias;
#pragma unroll
        for (int c = 0; c < CH; c += 4) {
            float4 w = *(const float4*)&projs[e][c];
            acc += w.x * zs[c][p];     acc += w.y * zs[c + 1][p];
            acc += w.z * zs[c + 2][p]; acc += w.w * zs[c + 3][p];
        }
        g_ze[(pbase + p) * EMB + e] = acc;
    }
}

// ---------------------------------------------------------------------------
// K1b: per-query eps2 = ||x|| * wmax / 64 + slack  (>=2x bf16 dot error bound)
// ---------------------------------------------------------------------------
__global__ __launch_bounds__(256) void k_xn() {
    int n = blockIdx.x * blockDim.x + threadIdx.x;
    const float4* p = (const float4*)(g_ze + (size_t)n * EMB);
    float s = 0.f;
#pragma unroll
    for (int i = 0; i < 16; ++i) {
        float4 v = p[i];
        s += v.x * v.x + v.y * v.y + v.z * v.z + v.w * v.w;
    }
    float wmax = __int_as_float(g_wmaxi);
    g_eps2[n] = sqrtf(s) * wmax * (1.0f / 64.0f) + 0.02f;
}

// ---------------------------------------------------------------------------
// K2: mma.sync bf16 coarse argmax + exact fp32 rescue
// Two-phase scan per tile: (1) tile max -> threshold (quad + cross-warp smem
// atomicMax), (2) append indices only. Candidates exact-rescored at the end.
// ---------------------------------------------------------------------------
#define NT  64             // 8192 / 128 code tiles
#define CAP 64
#define SM_B   0u          // 2 x 16384
#define SM_WN  32768u      // 8192 f32
#define SM_CI  65536u      // 128*CAP i32 = 32768
#define SM_CNT 98304u      // 128 i32
#define SM_THR 98816u      // 128 u32 (ordered-int thresholds)
#define SMEM_TOTAL 99328

__device__ __forceinline__ float exact_score(const float* __restrict__ qv,
                                             const float* __restrict__ ew, int idx) {
    const float4* w = (const float4*)(ew + (size_t)idx * EMB);
    float s = 0.f;
#pragma unroll
    for (int i = 0; i < 16; ++i) {
        float4 v = w[i];
        s = fmaf(qv[4 * i], v.x, s);
        s = fmaf(qv[4 * i + 1], v.y, s);
        s = fmaf(qv[4 * i + 2], v.z, s);
        s = fmaf(qv[4 * i + 3], v.w, s);
    }
    return s - __ldg(&g_wn[idx]);
}

__device__ __forceinline__ void load_btile(uint32_t dstbase, const char* srcbase,
                                           int tid) {
#pragma unroll
    for (int r = 0; r < 4; ++r) {
        int i = tid + 256 * r;          // chunk id 0..1023
        int n = i >> 3, c = i & 7;      // code row, 16B chunk
        uint32_t dst = dstbase + n * 128 + (((uint32_t)(c ^ (n & 7))) << 4);
        const char* src = srcbase + n * 128 + c * 16;
        asm volatile("cp.async.cg.shared.global [%0], [%1], 16;"
                     :: "r"(dst), "l"(src) : "memory");
    }
    asm volatile("cp.async.commit_group;" ::: "memory");
}

__global__ __launch_bounds__(256, 1) void k_argmax_mma(const float* __restrict__ ew) {
    extern __shared__ char smc[];
    float*    wns  = (float*)(smc + SM_WN);
    int*      cidx = (int*)(smc + SM_CI);
    int*      cnt  = (int*)(smc + SM_CNT);
    uint32_t* thrS = (uint32_t*)(smc + SM_THR);
    uint32_t sb = smem_u32(smc);

    int tid = threadIdx.x;
    int wid = tid >> 5, lane = tid & 31;
    int warpm = wid & 3, warpn = wid >> 2;
    int g = lane >> 2, tq = lane & 3;
    int qb = blockIdx.x * 128;

    if (tid < 128) { cnt[tid] = 0; thrS[tid] = fenc(-3.0e38f); }
    for (int i = tid; i < NCODE / 4; i += 256)
        ((float4*)wns)[i] = ((const float4*)g_wn)[i];

    // A fragments: built once from g_ze (fp32 -> bf16x2)
    uint32_t afr[2][4][4];
#pragma unroll
    for (int mt = 0; mt < 2; ++mt) {
        const float* r0 = g_ze + (size_t)(qb + warpm * 32 + mt * 16 + g) * EMB;
        const float* r1 = r0 + 8 * EMB;
#pragma unroll
        for (int ks = 0; ks < 4; ++ks) {
            float2 v;
            v = *(const float2*)(r0 + ks * 16 + 2 * tq);     afr[mt][ks][0] = bf2(v.x, v.y);
            v = *(const float2*)(r1 + ks * 16 + 2 * tq);     afr[mt][ks][1] = bf2(v.x, v.y);
            v = *(const float2*)(r0 + ks * 16 + 2 * tq + 8); afr[mt][ks][2] = bf2(v.x, v.y);
            v = *(const float2*)(r1 + ks * 16 + 2 * tq + 8); afr[mt][ks][3] = bf2(v.x, v.y);
        }
    }

    float eps2v[2][2], thr[2][2];
#pragma unroll
    for (int mt = 0; mt < 2; ++mt)
#pragma unroll
        for (int h = 0; h < 2; ++h) {
            eps2v[mt][h] = __ldg(&g_eps2[qb + warpm * 32 + mt * 16 + g + 8 * h]);
            thr[mt][h] = -3.0e38f;
        }

    int laneRow = lane & 7, laneTile = (lane >> 3) & 1;
    uint32_t rowoff = (uint32_t)laneRow * 128u;
    uint32_t cks[4];
#pragma unroll
    for (int ks = 0; ks < 4; ++ks)
        cks[ks] = ((uint32_t)((ks * 2 + laneTile) ^ laneRow)) << 4;

    // prologue: tile 0
    load_btile(sb + SM_B, (const char*)g_cb, tid);

    for (int t = 0; t < NT; ++t) {
        if (t + 1 < NT) {
            load_btile(sb + SM_B + (uint32_t)((t + 1) & 1) * 16384u,
                       (const char*)g_cb + (size_t)(t + 1) * 16384, tid);
            asm volatile("cp.async.wait_group 1;" ::: "memory");
        } else {
            asm volatile("cp.async.wait_group 0;" ::: "memory");
        }
        __syncthreads();

        float acc[2][8][4];
#pragma unroll
        for (int mt = 0; mt < 2; ++mt)
#pragma unroll
            for (int j = 0; j < 8; ++j)
#pragma unroll
                for (int k = 0; k < 4; ++k) acc[mt][j][k] = 0.f;

        uint32_t bbase = sb + SM_B + (uint32_t)(t & 1) * 16384u + rowoff
                       + (uint32_t)warpn * 8192u;   // warpn picks codes 0-63 / 64-127
#pragma unroll
        for (int j = 0; j < 8; ++j) {
#pragma unroll
            for (int ks = 0; ks < 4; ++ks) {
                uint32_t b0, b1;
                asm volatile("ldmatrix.sync.aligned.m8n8.x2.shared.b16 {%0,%1}, [%2];"
                             : "=r"(b0), "=r"(b1)
                             : "r"(bbase + (uint32_t)j * 1024u + cks[ks]));
                mma_bf16(acc[0][j], afr[0][ks], b0, b1);
                mma_bf16(acc[1][j], afr[1][ks], b0, b1);
            }
        }

        // convert accumulators to scores in place
        int cb0 = t * 128 + warpn * 64;
        int qlb = warpm * 32;
#pragma unroll
        for (int j = 0; j < 8; ++j) {
            float2 wn2 = *(const float2*)&wns[t * 128 + warpn * 64 + j * 8 + 2 * tq];
#pragma unroll
            for (int mt = 0; mt < 2; ++mt) {
                acc[mt][j][0] -= wn2.x; acc[mt][j][1] -= wn2.y;
                acc[mt][j][2] -= wn2.x; acc[mt][j][3] -= wn2.y;
            }
        }

        // pass 1: tile max -> threshold (quad + cross-warp smem share)
#pragma unroll
        for (int mt = 0; mt < 2; ++mt) {
            float m0 = -3.0e38f, m1 = -3.0e38f;
#pragma unroll
            for (int j = 0; j < 8; ++j) {
                m0 = fmaxf(m0, fmaxf(acc[mt][j][0], acc[mt][j][1]));
                m1 = fmaxf(m1, fmaxf(acc[mt][j][2], acc[mt][j][3]));
            }
            m0 = fmaxf(m0, __shfl_xor_sync(0xffffffffu, m0, 1));
            m0 = fmaxf(m0, __shfl_xor_sync(0xffffffffu, m0, 2));
            m1 = fmaxf(m1, __shfl_xor_sync(0xffffffffu, m1, 1));
            m1 = fmaxf(m1, __shfl_xor_sync(0xffffffffu, m1, 2));
            thr[mt][0] = fmaxf(thr[mt][0], m0 - eps2v[mt][0]);
            thr[mt][1] = fmaxf(thr[mt][1], m1 - eps2v[mt][1]);
            int ql = qlb + mt * 16 + g;
            atomicMax(&thrS[ql], fenc(thr[mt][0]));
            atomicMax(&thrS[ql + 8], fenc(thr[mt][1]));
            thr[mt][0] = fmaxf(thr[mt][0], fdec(thrS[ql]));
            thr[mt][1] = fmaxf(thr[mt][1], fdec(thrS[ql + 8]));
        }

        // pass 2: append candidate indices only
#pragma unroll
        for (int j = 0; j < 8; ++j) {
            int col0 = cb0 + j * 8 + 2 * tq;
#pragma unroll
            for (int mt = 0; mt < 2; ++mt) {
                int ql = qlb + mt * 16 + g;
                if (acc[mt][j][0] > thr[mt][0]) {
                    int p = atomicAdd(&cnt[ql], 1);
                    if (p < CAP) cidx[ql * CAP + p] = col0;
                }
                if (acc[mt][j][1] > thr[mt][0]) {
                    int p = atomicAdd(&cnt[ql], 1);
                    if (p < CAP) cidx[ql * CAP + p] = col0 + 1;
                }
                if (acc[mt][j][2] > thr[mt][1]) {
                    int p = atomicAdd(&cnt[ql + 8], 1);
                    if (p < CAP) cidx[(ql + 8) * CAP + p] = col0;
                }
                if (acc[mt][j][3] > thr[mt][1]) {
                    int p = atomicAdd(&cnt[ql + 8], 1);
                    if (p < CAP) cidx[(ql + 8) * CAP + p] = col0 + 1;
                }
            }
        }
        __syncthreads();
    }

    // final: exact fp32 rescore of all candidates (order-independent)
    if (tid < 128) {
        int q = tid, n = qb + q;
        int c = cnt[q];
        float qv[64];
        const float4* qp = (const float4*)(g_ze + (size_t)n * EMB);
#pragma unroll
        for (int i = 0; i < 16; ++i) {
            float4 v = qp[i];
            qv[4 * i] = v.x; qv[4 * i + 1] = v.y;
            qv[4 * i + 2] = v.z; qv[4 * i + 3] = v.w;
        }
        float bv = -3.0e38f;
        int bi = 0x7fffffff;
        if (c > CAP) {  // overflow fallback: exact full scan (should be ~never)
            for (int id = 0; id < NCODE; ++id) {
                float s = exact_score(qv, ew, id);
                if (s > bv) { bv = s; bi = id; }
            }
        } else {
            for (int k = 0; k < c; ++k) {
                int id = cidx[q * CAP + k];
                float s = exact_score(qv, ew, id);
                if (s > bv || (s == bv && id < bi)) { bv = s; bi = id; }
            }
        }
        g_ind[n] = bi;
    }
}

// ---------------------------------------------------------------------------
// K3: gather + outputs + loss partials
// ---------------------------------------------------------------------------
__global__ __launch_bounds__(256) void k_gather(const float* __restrict__ ew,
                                                float* __restrict__ out,
                                                int full_out) {
    int tid = threadIdx.x;
    int n = blockIdx.x * 4 + (tid >> 6);
    int e = tid & 63;
    int idx = g_ind[n];
    float v = ew[idx * EMB + e];
    float d = v - g_ze[n * EMB + e];
    int b = n >> 10;
    int hw = n & 1023;
    out[b * (EMB * HW) + e * HW + hw] = v;
    if (full_out) {
        out[N_PIX * EMB + n * EMB + e] = v;
        if (e == 0) out[2 * N_PIX * EMB + 1 + n] = (float)idx;
    }
    float s = d * d;
#pragma unroll
    for (int off = 16; off > 0; off >>= 1)
        s += __shfl_down_sync(0xffffffffu, s, off);
    __shared__ float ps[8];
    if ((tid & 31) == 0) ps[tid >> 5] = s;
    __syncthreads();
    if (tid < 8) {
        s = ps[tid];
#pragma unroll
        for (int off = 4; off > 0; off >>= 1)
            s += __shfl_down_sync(0xffu, s, off);
        if (tid == 0) atomicAdd(&g_loss, s);
    }
}

__global__ void k_fin(float* __restrict__ out, int full_out) {
    if (full_out)
        out[2 * N_PIX * EMB] = 12.5f * g_loss / (float)(N_PIX * EMB);
}

// ---------------------------------------------------------------------------
extern "C" void kernel_launch(void* const* d_in, const int* in_sizes, int n_in,
                              void* d_out, int out_size) {
    const float* z  = (const float*)d_in[0];
    const float* pw = (const float*)d_in[1];
    const float* pb = (const float*)d_in[2];
    const float* ew = (const float*)d_in[3];
    float* out = (float*)d_out;

    int full_out = (out_size >= 2 * N_PIX * EMB + 1 + N_PIX) ? 1 : 0;

    cudaFuncSetAttribute(k_argmax_mma, cudaFuncAttributeMaxDynamicSharedMemorySize,
                         SMEM_TOTAL);

    k_wn<<<NCODE / 256, 256>>>(ew);
    k_proj<<<N_PIX / 16, 256>>>(z, pw, pb);
    k_xn<<<N_PIX / 256, 256>>>();
    k_argmax_mma<<<N_PIX / 128, 256, SMEM_TOTAL>>>(ew);
    k_gather<<<N_PIX / 4, 256>>>(ew, out, full_out);
    k_fin<<<1, 1>>>(out, full_out);
}

// round 14
// speedup vs baseline: 20.6005x; 1.3554x over previous
#include <cuda_runtime.h>
#include <cuda_bf16.h>
#include <cstdint>

#define N_PIX 32768   // B*H*W
#define EMB   64
#define CH    128
#define NCODE 8192
#define HW    1024

// ---------------------------------------------------------------------------
// scratch (no allocations allowed)
// ---------------------------------------------------------------------------
__device__ float         g_ze[N_PIX * EMB];     // queries fp32, 8 MB
__device__ int           g_ind[N_PIX];
__device__ float         g_wn[NCODE];           // 0.5*||w||^2 fp32
__device__ __nv_bfloat16 g_cb[NCODE * EMB];     // codebook bf16 row-major
__device__ int           g_wmaxi = 0;
__device__ float         g_loss;

__device__ __forceinline__ uint32_t smem_u32(const void* p) {
    uint32_t a;
    asm("{ .reg .u64 t; cvta.to.shared.u64 t, %1; cvt.u32.u64 %0, t; }"
        : "=r"(a) : "l"(p));
    return a;
}
__device__ __forceinline__ uint32_t bf2(float lo, float hi) {
    uint32_t r;
    asm("cvt.rn.bf16x2.f32 %0, %1, %2;" : "=r"(r) : "f"(hi), "f"(lo));
    return r;
}
__device__ __forceinline__ void mma_bf16(float* c, const uint32_t* a,
                                         uint32_t b0, uint32_t b1) {
    asm volatile(
        "mma.sync.aligned.m16n8k16.row.col.f32.bf16.bf16.f32 "
        "{%0,%1,%2,%3},{%4,%5,%6,%7},{%8,%9},{%0,%1,%2,%3};"
        : "+f"(c[0]), "+f"(c[1]), "+f"(c[2]), "+f"(c[3])
        : "r"(a[0]), "r"(a[1]), "r"(a[2]), "r"(a[3]), "r"(b0), "r"(b1));
}

// ---------------------------------------------------------------------------
// K0: code half-norms fp32, bf16 codebook, max norm, zero loss
// ---------------------------------------------------------------------------
__global__ void k_wn(const float* __restrict__ ew) {
    int j = blockIdx.x * blockDim.x + threadIdx.x;
    const float4* p = (const float4*)(ew + (size_t)j * EMB);
    uint4 packed[8];
    float s = 0.f;
#pragma unroll
    for (int i = 0; i < 8; ++i) {
        float4 a = p[2 * i], b = p[2 * i + 1];
        s += a.x * a.x + a.y * a.y + a.z * a.z + a.w * a.w;
        s += b.x * b.x + b.y * b.y + b.z * b.z + b.w * b.w;
        packed[i] = make_uint4(bf2(a.x, a.y), bf2(a.z, a.w),
                               bf2(b.x, b.y), bf2(b.z, b.w));
    }
    uint4* dst = (uint4*)(g_cb + (size_t)j * EMB);
#pragma unroll
    for (int i = 0; i < 8; ++i) dst[i] = packed[i];
    g_wn[j] = 0.5f * s;
    atomicMax(&g_wmaxi, __float_as_int(sqrtf(s)));
    if (j == 0) g_loss = 0.f;
}

// ---------------------------------------------------------------------------
// K1: projection -> g_ze fp32
// ---------------------------------------------------------------------------
__global__ __launch_bounds__(256) void k_proj(const float* __restrict__ z,
                                              const float* __restrict__ pw,
                                              const float* __restrict__ pb) {
    __shared__ float projs[EMB][CH + 4];
    __shared__ float zs[CH][18];
    int tid = threadIdx.x;
    int pbase = blockIdx.x * 16;
    for (int i = tid; i < EMB * CH / 4; i += 256) {
        int e = i >> 5;
        int c4 = (i & 31) << 2;
        float4 v = ((const float4*)pw)[i];
        projs[e][c4] = v.x; projs[e][c4 + 1] = v.y;
        projs[e][c4 + 2] = v.z; projs[e][c4 + 3] = v.w;
    }
    for (int i = tid; i < CH * 16; i += 256) {
        int c = i >> 4, p = i & 15, n = pbase + p;
        zs[c][p] = z[(n >> 10) * (CH * HW) + c * HW + (n & 1023)];
    }
    __syncthreads();
    int e = tid & 63, pg = tid >> 6;
    float bias = pb[e];
    for (int p = pg; p < 16; p += 4) {
        float acc = bias;
#pragma unroll
        for (int c = 0; c < CH; c += 4) {
            float4 w = *(const float4*)&projs[e][c];
            acc += w.x * zs[c][p];     acc += w.y * zs[c + 1][p];
            acc += w.z * zs[c + 2][p]; acc += w.w * zs[c + 3][p];
        }
        g_ze[(pbase + p) * EMB + e] = acc;
    }
}

// ---------------------------------------------------------------------------
// K2: mma.sync bf16 coarse argmax + exact fp32 rescue.
// 8 warps, each owns 16 queries x full 128-code tile (single-owner thresholds,
// no cross-warp sharing). 2 CTAs/SM (regs<=128, smem 82KB) -> single wave.
// ---------------------------------------------------------------------------
#define NT  64             // 8192 / 128 code tiles
#define CAP 32
#define SM_B   0u          // 2 x 16384
#define SM_WN  32768u      // 8192 f32
#define SM_CI  65536u      // 128*CAP i32 = 16384
#define SM_CNT 81920u      // 128 i32
#define SMEM_TOTAL 82432

__device__ __forceinline__ float exact_score(const float* __restrict__ qv,
                                             const float* __restrict__ ew, int idx) {
    const float4* w = (const float4*)(ew + (size_t)idx * EMB);
    float s = 0.f;
#pragma unroll
    for (int i = 0; i < 16; ++i) {
        float4 v = w[i];
        s = fmaf(qv[4 * i], v.x, s);
        s = fmaf(qv[4 * i + 1], v.y, s);
        s = fmaf(qv[4 * i + 2], v.z, s);
        s = fmaf(qv[4 * i + 3], v.w, s);
    }
    return s - __ldg(&g_wn[idx]);
}

__device__ __forceinline__ void load_btile(uint32_t dstbase, const char* srcbase,
                                           int tid) {
#pragma unroll
    for (int r = 0; r < 4; ++r) {
        int i = tid + 256 * r;          // chunk id 0..1023
        int n = i >> 3, c = i & 7;      // code row, 16B chunk
        uint32_t dst = dstbase + n * 128 + (((uint32_t)(c ^ (n & 7))) << 4);
        const char* src = srcbase + n * 128 + c * 16;
        asm volatile("cp.async.cg.shared.global [%0], [%1], 16;"
                     :: "r"(dst), "l"(src) : "memory");
    }
    asm volatile("cp.async.commit_group;" ::: "memory");
}

__global__ __launch_bounds__(256, 2) void k_argmax_mma(const float* __restrict__ ew) {
    extern __shared__ char smc[];
    float* wns  = (float*)(smc + SM_WN);
    int*   cidx = (int*)(smc + SM_CI);
    int*   cnt  = (int*)(smc + SM_CNT);
    uint32_t sb = smem_u32(smc);

    int tid = threadIdx.x;
    int wid = tid >> 5, lane = tid & 31;
    int g = lane >> 2, tq = lane & 3;
    int qb = blockIdx.x * 128;

    if (tid < 128) cnt[tid] = 0;
    for (int i = tid; i < NCODE / 4; i += 256)
        ((float4*)wns)[i] = ((const float4*)g_wn)[i];

    // A fragments (16 query rows per warp) + ||x||^2 partials for eps
    uint32_t afr[4][4];
    float sum0 = 0.f, sum1 = 0.f;
    {
        const float* r0 = g_ze + (size_t)(qb + wid * 16 + g) * EMB;
        const float* r1 = r0 + 8 * EMB;
#pragma unroll
        for (int ks = 0; ks < 4; ++ks) {
            float2 v;
            v = *(const float2*)(r0 + ks * 16 + 2 * tq);
            afr[ks][0] = bf2(v.x, v.y); sum0 += v.x * v.x + v.y * v.y;
            v = *(const float2*)(r1 + ks * 16 + 2 * tq);
            afr[ks][1] = bf2(v.x, v.y); sum1 += v.x * v.x + v.y * v.y;
            v = *(const float2*)(r0 + ks * 16 + 2 * tq + 8);
            afr[ks][2] = bf2(v.x, v.y); sum0 += v.x * v.x + v.y * v.y;
            v = *(const float2*)(r1 + ks * 16 + 2 * tq + 8);
            afr[ks][3] = bf2(v.x, v.y); sum1 += v.x * v.x + v.y * v.y;
        }
    }
    sum0 += __shfl_xor_sync(0xffffffffu, sum0, 1);
    sum0 += __shfl_xor_sync(0xffffffffu, sum0, 2);
    sum1 += __shfl_xor_sync(0xffffffffu, sum1, 1);
    sum1 += __shfl_xor_sync(0xffffffffu, sum1, 2);
    float wmax = __int_as_float(__ldg(&g_wmaxi));
    float eps0 = sqrtf(sum0) * wmax * (1.0f / 64.0f) + 0.02f;
    float eps1 = sqrtf(sum1) * wmax * (1.0f / 64.0f) + 0.02f;
    float thr0 = -3.0e38f, thr1 = -3.0e38f;

    int laneRow = lane & 7, laneTile = (lane >> 3) & 1;
    uint32_t rowoff = (uint32_t)laneRow * 128u;
    uint32_t cks[4];
#pragma unroll
    for (int ks = 0; ks < 4; ++ks)
        cks[ks] = ((uint32_t)((ks * 2 + laneTile) ^ laneRow)) << 4;

    // prologue: tile 0
    load_btile(sb + SM_B, (const char*)g_cb, tid);

    for (int t = 0; t < NT; ++t) {
        if (t + 1 < NT) {
            load_btile(sb + SM_B + (uint32_t)((t + 1) & 1) * 16384u,
                       (const char*)g_cb + (size_t)(t + 1) * 16384, tid);
            asm volatile("cp.async.wait_group 1;" ::: "memory");
        } else {
            asm volatile("cp.async.wait_group 0;" ::: "memory");
        }
        __syncthreads();

        float acc[16][4];
#pragma unroll
        for (int j = 0; j < 16; ++j)
#pragma unroll
            for (int k = 0; k < 4; ++k) acc[j][k] = 0.f;

        uint32_t bbase = sb + SM_B + (uint32_t)(t & 1) * 16384u + rowoff;
#pragma unroll
        for (int j = 0; j < 16; ++j) {
#pragma unroll
            for (int ks = 0; ks < 4; ++ks) {
                uint32_t b0, b1;
                asm volatile("ldmatrix.sync.aligned.m8n8.x2.shared.b16 {%0,%1}, [%2];"
                             : "=r"(b0), "=r"(b1)
                             : "r"(bbase + (uint32_t)j * 1024u + cks[ks]));
                mma_bf16(acc[j], afr[ks], b0, b1);
            }
        }

        // scores in place: subtract 0.5||w||^2
#pragma unroll
        for (int j = 0; j < 16; ++j) {
            float2 wn2 = *(const float2*)&wns[t * 128 + j * 8 + 2 * tq];
            acc[j][0] -= wn2.x; acc[j][1] -= wn2.y;
            acc[j][2] -= wn2.x; acc[j][3] -= wn2.y;
        }

        // pass 1: tile max -> threshold (quad share; rows owned by one warp)
        {
            float m0 = -3.0e38f, m1 = -3.0e38f;
#pragma unroll
            for (int j = 0; j < 16; ++j) {
                m0 = fmaxf(m0, fmaxf(acc[j][0], acc[j][1]));
                m1 = fmaxf(m1, fmaxf(acc[j][2], acc[j][3]));
            }
            m0 = fmaxf(m0, __shfl_xor_sync(0xffffffffu, m0, 1));
            m0 = fmaxf(m0, __shfl_xor_sync(0xffffffffu, m0, 2));
            m1 = fmaxf(m1, __shfl_xor_sync(0xffffffffu, m1, 1));
            m1 = fmaxf(m1, __shfl_xor_sync(0xffffffffu, m1, 2));
            thr0 = fmaxf(thr0, m0 - eps0);
            thr1 = fmaxf(thr1, m1 - eps1);
        }

        // pass 2: append candidate indices only
        int ql0 = wid * 16 + g, ql1 = ql0 + 8;
#pragma unroll
        for (int j = 0; j < 16; ++j) {
            int col0 = t * 128 + j * 8 + 2 * tq;
            if (acc[j][0] > thr0) {
                int p = atomicAdd(&cnt[ql0], 1);
                if (p < CAP) cidx[ql0 * CAP + p] = col0;
            }
            if (acc[j][1] > thr0) {
                int p = atomicAdd(&cnt[ql0], 1);
                if (p < CAP) cidx[ql0 * CAP + p] = col0 + 1;
            }
            if (acc[j][2] > thr1) {
                int p = atomicAdd(&cnt[ql1], 1);
                if (p < CAP) cidx[ql1 * CAP + p] = col0;
            }
            if (acc[j][3] > thr1) {
                int p = atomicAdd(&cnt[ql1], 1);
                if (p < CAP) cidx[ql1 * CAP + p] = col0 + 1;
            }
        }
        __syncthreads();
    }

    // final: exact fp32 rescore of all candidates (order-independent)
    if (tid < 128) {
        int q = tid, n = qb + q;
        int c = cnt[q];
        float qv[64];
        const float4* qp = (const float4*)(g_ze + (size_t)n * EMB);
#pragma unroll
        for (int i = 0; i < 16; ++i) {
            float4 v = qp[i];
            qv[4 * i] = v.x; qv[4 * i + 1] = v.y;
            qv[4 * i + 2] = v.z; qv[4 * i + 3] = v.w;
        }
        float bv = -3.0e38f;
        int bi = 0x7fffffff;
        if (c > CAP) {  // overflow fallback: exact full scan (should be ~never)
            for (int id = 0; id < NCODE; ++id) {
                float s = exact_score(qv, ew, id);
                if (s > bv) { bv = s; bi = id; }
            }
        } else {
            for (int k = 0; k < c; ++k) {
                int id = cidx[q * CAP + k];
                float s = exact_score(qv, ew, id);
                if (s > bv || (s == bv && id < bi)) { bv = s; bi = id; }
            }
        }
        g_ind[n] = bi;
    }
}

// ---------------------------------------------------------------------------
// K3: gather + outputs + loss partials
// ---------------------------------------------------------------------------
__global__ __launch_bounds__(256) void k_gather(const float* __restrict__ ew,
                                                float* __restrict__ out,
                                                int full_out) {
    int tid = threadIdx.x;
    int n = blockIdx.x * 4 + (tid >> 6);
    int e = tid & 63;
    int idx = g_ind[n];
    float v = ew[idx * EMB + e];
    float d = v - g_ze[n * EMB + e];
    int b = n >> 10;
    int hw = n & 1023;
    out[b * (EMB * HW) + e * HW + hw] = v;
    if (full_out) {
        out[N_PIX * EMB + n * EMB + e] = v;
        if (e == 0) out[2 * N_PIX * EMB + 1 + n] = (float)idx;
    }
    float s = d * d;
#pragma unroll
    for (int off = 16; off > 0; off >>= 1)
        s += __shfl_down_sync(0xffffffffu, s, off);
    __shared__ float ps[8];
    if ((tid & 31) == 0) ps[tid >> 5] = s;
    __syncthreads();
    if (tid < 8) {
        s = ps[tid];
#pragma unroll
        for (int off = 4; off > 0; off >>= 1)
            s += __shfl_down_sync(0xffu, s, off);
        if (tid == 0) atomicAdd(&g_loss, s);
    }
}

__global__ void k_fin(float* __restrict__ out, int full_out) {
    if (full_out)
        out[2 * N_PIX * EMB] = 12.5f * g_loss / (float)(N_PIX * EMB);
}

// ---------------------------------------------------------------------------
extern "C" void kernel_launch(void* const* d_in, const int* in_sizes, int n_in,
                              void* d_out, int out_size) {
    const float* z  = (const float*)d_in[0];
    const float* pw = (const float*)d_in[1];
    const float* pb = (const float*)d_in[2];
    const float* ew = (const float*)d_in[3];
    float* out = (float*)d_out;

    int full_out = (out_size >= 2 * N_PIX * EMB + 1 + N_PIX) ? 1 : 0;

    cudaFuncSetAttribute(k_argmax_mma, cudaFuncAttributeMaxDynamicSharedMemorySize,
                         SMEM_TOTAL);

    k_wn<<<NCODE / 256, 256>>>(ew);
    k_proj<<<N_PIX / 16, 256>>>(z, pw, pb);
    k_argmax_mma<<<N_PIX / 128, 256, SMEM_TOTAL>>>(ew);
    k_gather<<<N_PIX / 4, 256>>>(ew, out, full_out);
    k_fin<<<1, 1>>>(out, full_out);
}

// round 15
// speedup vs baseline: 21.0467x; 1.0217x over previous
#include <cuda_runtime.h>
#include <cuda_bf16.h>
#include <cstdint>

#define N_PIX 32768   // B*H*W
#define EMB   64
#define CH    128
#define NCODE 8192
#define HW    1024

// ---------------------------------------------------------------------------
// scratch (no allocations allowed)
// ---------------------------------------------------------------------------
__device__ float         g_ze[N_PIX * EMB];     // queries fp32, 8 MB
__device__ int           g_ind[N_PIX];
__device__ float         g_wn[NCODE];           // 0.5*||w||^2 fp32
__device__ __nv_bfloat16 g_cb[NCODE * EMB];     // codebook bf16 row-major
__device__ int           g_wmaxi = 0;
__device__ float         g_loss;

__device__ __forceinline__ uint32_t smem_u32(const void* p) {
    uint32_t a;
    asm("{ .reg .u64 t; cvta.to.shared.u64 t, %1; cvt.u32.u64 %0, t; }"
        : "=r"(a) : "l"(p));
    return a;
}
__device__ __forceinline__ uint32_t bf2(float lo, float hi) {
    uint32_t r;
    asm("cvt.rn.bf16x2.f32 %0, %1, %2;" : "=r"(r) : "f"(hi), "f"(lo));
    return r;
}
__device__ __forceinline__ void mma_bf16(float* c, const uint32_t* a,
                                         uint32_t b0, uint32_t b1) {
    asm volatile(
        "mma.sync.aligned.m16n8k16.row.col.f32.bf16.bf16.f32 "
        "{%0,%1,%2,%3},{%4,%5,%6,%7},{%8,%9},{%0,%1,%2,%3};"
        : "+f"(c[0]), "+f"(c[1]), "+f"(c[2]), "+f"(c[3])
        : "r"(a[0]), "r"(a[1]), "r"(a[2]), "r"(a[3]), "r"(b0), "r"(b1));
}

// ---------------------------------------------------------------------------
// K0: code half-norms fp32, bf16 codebook, max norm, zero loss
// ---------------------------------------------------------------------------
__global__ void k_wn(const float* __restrict__ ew) {
    int j = blockIdx.x * blockDim.x + threadIdx.x;
    const float4* p = (const float4*)(ew + (size_t)j * EMB);
    uint4 packed[8];
    float s = 0.f;
#pragma unroll
    for (int i = 0; i < 8; ++i) {
        float4 a = p[2 * i], b = p[2 * i + 1];
        s += a.x * a.x + a.y * a.y + a.z * a.z + a.w * a.w;
        s += b.x * b.x + b.y * b.y + b.z * b.z + b.w * b.w;
        packed[i] = make_uint4(bf2(a.x, a.y), bf2(a.z, a.w),
                               bf2(b.x, b.y), bf2(b.z, b.w));
    }
    uint4* dst = (uint4*)(g_cb + (size_t)j * EMB);
#pragma unroll
    for (int i = 0; i < 8; ++i) dst[i] = packed[i];
    g_wn[j] = 0.5f * s;
    atomicMax(&g_wmaxi, __float_as_int(sqrtf(s)));
    if (j == 0) g_loss = 0.f;
}

// ---------------------------------------------------------------------------
// K1: projection -> g_ze fp32
// ---------------------------------------------------------------------------
__global__ __launch_bounds__(256) void k_proj(const float* __restrict__ z,
                                              const float* __restrict__ pw,
                                              const float* __restrict__ pb) {
    __shared__ float projs[EMB][CH + 4];
    __shared__ float zs[CH][18];
    int tid = threadIdx.x;
    int pbase = blockIdx.x * 16;
    for (int i = tid; i < EMB * CH / 4; i += 256) {
        int e = i >> 5;
        int c4 = (i & 31) << 2;
        float4 v = ((const float4*)pw)[i];
        projs[e][c4] = v.x; projs[e][c4 + 1] = v.y;
        projs[e][c4 + 2] = v.z; projs[e][c4 + 3] = v.w;
    }
    for (int i = tid; i < CH * 16; i += 256) {
        int c = i >> 4, p = i & 15, n = pbase + p;
        zs[c][p] = z[(n >> 10) * (CH * HW) + c * HW + (n & 1023)];
    }
    __syncthreads();
    int e = tid & 63, pg = tid >> 6;
    float bias = pb[e];
    for (int p = pg; p < 16; p += 4) {
        float acc = bias;
#pragma unroll
        for (int c = 0; c < CH; c += 4) {
            float4 w = *(const float4*)&projs[e][c];
            acc += w.x * zs[c][p];     acc += w.y * zs[c + 1][p];
            acc += w.z * zs[c + 2][p]; acc += w.w * zs[c + 3][p];
        }
        g_ze[(pbase + p) * EMB + e] = acc;
    }
}

// ---------------------------------------------------------------------------
// K2: mma.sync bf16 coarse argmax + exact fp32 rescue.
// 8 warps x (16q x 128c); ldmatrix.x4; ballot-skip append pass; 3-stage
// cp.async pipeline; 2 CTAs/SM.
// ---------------------------------------------------------------------------
#define NT  64             // 8192 / 128 code tiles
#define CAP 32
#define SM_B   0u          // 3 x 16384 = 49152
#define SM_WN  49152u      // 8192 f32 = 32768
#define SM_CI  81920u      // 128*CAP i32 = 16384
#define SM_CNT 98304u      // 128 i32
#define SMEM_TOTAL 99072

__device__ __forceinline__ float exact_score(const float* __restrict__ qv,
                                             const float* __restrict__ ew, int idx) {
    const float4* w = (const float4*)(ew + (size_t)idx * EMB);
    float s = 0.f;
#pragma unroll
    for (int i = 0; i < 16; ++i) {
        float4 v = w[i];
        s = fmaf(qv[4 * i], v.x, s);
        s = fmaf(qv[4 * i + 1], v.y, s);
        s = fmaf(qv[4 * i + 2], v.z, s);
        s = fmaf(qv[4 * i + 3], v.w, s);
    }
    return s - __ldg(&g_wn[idx]);
}

__device__ __forceinline__ void load_btile(uint32_t dstbase, const char* srcbase,
                                           int tid) {
#pragma unroll
    for (int r = 0; r < 4; ++r) {
        int i = tid + 256 * r;          // chunk id 0..1023
        int n = i >> 3, c = i & 7;      // code row, 16B chunk
        uint32_t dst = dstbase + n * 128 + (((uint32_t)(c ^ (n & 7))) << 4);
        const char* src = srcbase + n * 128 + c * 16;
        asm volatile("cp.async.cg.shared.global [%0], [%1], 16;"
                     :: "r"(dst), "l"(src) : "memory");
    }
    asm volatile("cp.async.commit_group;" ::: "memory");
}

__global__ __launch_bounds__(256, 2) void k_argmax_mma(const float* __restrict__ ew) {
    extern __shared__ char smc[];
    float* wns  = (float*)(smc + SM_WN);
    int*   cidx = (int*)(smc + SM_CI);
    int*   cnt  = (int*)(smc + SM_CNT);
    uint32_t sb = smem_u32(smc);

    int tid = threadIdx.x;
    int wid = tid >> 5, lane = tid & 31;
    int g = lane >> 2, tq = lane & 3;
    int qb = blockIdx.x * 128;

    if (tid < 128) cnt[tid] = 0;
    for (int i = tid; i < NCODE / 4; i += 256)
        ((float4*)wns)[i] = ((const float4*)g_wn)[i];

    // A fragments (16 query rows per warp) + ||x||^2 partials for eps
    uint32_t afr[4][4];
    float sum0 = 0.f, sum1 = 0.f;
    {
        const float* r0 = g_ze + (size_t)(qb + wid * 16 + g) * EMB;
        const float* r1 = r0 + 8 * EMB;
#pragma unroll
        for (int ks = 0; ks < 4; ++ks) {
            float2 v;
            v = *(const float2*)(r0 + ks * 16 + 2 * tq);
            afr[ks][0] = bf2(v.x, v.y); sum0 += v.x * v.x + v.y * v.y;
            v = *(const float2*)(r1 + ks * 16 + 2 * tq);
            afr[ks][1] = bf2(v.x, v.y); sum1 += v.x * v.x + v.y * v.y;
            v = *(const float2*)(r0 + ks * 16 + 2 * tq + 8);
            afr[ks][2] = bf2(v.x, v.y); sum0 += v.x * v.x + v.y * v.y;
            v = *(const float2*)(r1 + ks * 16 + 2 * tq + 8);
            afr[ks][3] = bf2(v.x, v.y); sum1 += v.x * v.x + v.y * v.y;
        }
    }
    sum0 += __shfl_xor_sync(0xffffffffu, sum0, 1);
    sum0 += __shfl_xor_sync(0xffffffffu, sum0, 2);
    sum1 += __shfl_xor_sync(0xffffffffu, sum1, 1);
    sum1 += __shfl_xor_sync(0xffffffffu, sum1, 2);
    float wmax = __int_as_float(__ldg(&g_wmaxi));
    float eps0 = sqrtf(sum0) * wmax * (1.0f / 64.0f) + 0.02f;
    float eps1 = sqrtf(sum1) * wmax * (1.0f / 64.0f) + 0.02f;
    float thr0 = -3.0e38f, thr1 = -3.0e38f;

    // ldmatrix.x4 addressing: lane quads q4=0..3 pick chunks (q4) and (4+q4)
    int laneRow = lane & 7;
    int q4 = (lane >> 3) & 3;
    uint32_t off0 = (uint32_t)laneRow * 128u
                  + (((uint32_t)(q4 ^ laneRow)) << 4);        // ks 0,1
    uint32_t off1 = (uint32_t)laneRow * 128u
                  + (((uint32_t)((4 + q4) ^ laneRow)) << 4);  // ks 2,3

    // prologue: tiles 0,1
    load_btile(sb + SM_B, (const char*)g_cb, tid);
    load_btile(sb + SM_B + 16384u, (const char*)g_cb + 16384, tid);

    for (int t = 0; t < NT; ++t) {
        if (t + 2 < NT) {
            load_btile(sb + SM_B + (uint32_t)((t + 2) % 3) * 16384u,
                       (const char*)g_cb + (size_t)(t + 2) * 16384, tid);
            asm volatile("cp.async.wait_group 2;" ::: "memory");
        } else if (t + 1 < NT) {
            asm volatile("cp.async.wait_group 1;" ::: "memory");
        } else {
            asm volatile("cp.async.wait_group 0;" ::: "memory");
        }
        __syncthreads();

        float acc[16][4];
#pragma unroll
        for (int j = 0; j < 16; ++j)
#pragma unroll
            for (int k = 0; k < 4; ++k) acc[j][k] = 0.f;

        uint32_t bbase = sb + SM_B + (uint32_t)(t % 3) * 16384u;
#pragma unroll
        for (int j = 0; j < 16; ++j) {
            uint32_t jb = bbase + (uint32_t)j * 1024u;
            uint32_t b0, b1, b2, b3;
            asm volatile("ldmatrix.sync.aligned.m8n8.x4.shared.b16 {%0,%1,%2,%3}, [%4];"
                         : "=r"(b0), "=r"(b1), "=r"(b2), "=r"(b3)
                         : "r"(jb + off0));
            mma_bf16(acc[j], afr[0], b0, b1);
            mma_bf16(acc[j], afr[1], b2, b3);
            asm volatile("ldmatrix.sync.aligned.m8n8.x4.shared.b16 {%0,%1,%2,%3}, [%4];"
                         : "=r"(b0), "=r"(b1), "=r"(b2), "=r"(b3)
                         : "r"(jb + off1));
            mma_bf16(acc[j], afr[2], b0, b1);
            mma_bf16(acc[j], afr[3], b2, b3);
        }

        // scores in place: subtract 0.5||w||^2
#pragma unroll
        for (int j = 0; j < 16; ++j) {
            float2 wn2 = *(const float2*)&wns[t * 128 + j * 8 + 2 * tq];
            acc[j][0] -= wn2.x; acc[j][1] -= wn2.y;
            acc[j][2] -= wn2.x; acc[j][3] -= wn2.y;
        }

        // pass 1: tile max -> threshold (quad share; rows owned by one warp)
        float thr0_old = thr0, thr1_old = thr1;
        {
            float m0 = -3.0e38f, m1 = -3.0e38f;
#pragma unroll
            for (int j = 0; j < 16; ++j) {
                m0 = fmaxf(m0, fmaxf(acc[j][0], acc[j][1]));
                m1 = fmaxf(m1, fmaxf(acc[j][2], acc[j][3]));
            }
            m0 = fmaxf(m0, __shfl_xor_sync(0xffffffffu, m0, 1));
            m0 = fmaxf(m0, __shfl_xor_sync(0xffffffffu, m0, 2));
            m1 = fmaxf(m1, __shfl_xor_sync(0xffffffffu, m1, 1));
            m1 = fmaxf(m1, __shfl_xor_sync(0xffffffffu, m1, 2));
            thr0 = fmaxf(thr0, m0 - eps0);
            thr1 = fmaxf(thr1, m1 - eps1);
            // tile contains a candidate iff a row-max beats the OLD threshold
            if (!__ballot_sync(0xffffffffu,
                               (m0 > thr0_old) || (m1 > thr1_old))) {
                __syncthreads();
                continue;
            }
        }

        // pass 2: append candidate indices only
        int ql0 = wid * 16 + g, ql1 = ql0 + 8;
#pragma unroll
        for (int j = 0; j < 16; ++j) {
            int col0 = t * 128 + j * 8 + 2 * tq;
            if (acc[j][0] > thr0) {
                int p = atomicAdd(&cnt[ql0], 1);
                if (p < CAP) cidx[ql0 * CAP + p] = col0;
            }
            if (acc[j][1] > thr0) {
                int p = atomicAdd(&cnt[ql0], 1);
                if (p < CAP) cidx[ql0 * CAP + p] = col0 + 1;
            }
            if (acc[j][2] > thr1) {
                int p = atomicAdd(&cnt[ql1], 1);
                if (p < CAP) cidx[ql1 * CAP + p] = col0;
            }
            if (acc[j][3] > thr1) {
                int p = atomicAdd(&cnt[ql1], 1);
                if (p < CAP) cidx[ql1 * CAP + p] = col0 + 1;
            }
        }
        __syncthreads();
    }

    // final: exact fp32 rescore of all candidates (order-independent)
    if (tid < 128) {
        int q = tid, n = qb + q;
        int c = cnt[q];
        float qv[64];
        const float4* qp = (const float4*)(g_ze + (size_t)n * EMB);
#pragma unroll
        for (int i = 0; i < 16; ++i) {
            float4 v = qp[i];
            qv[4 * i] = v.x; qv[4 * i + 1] = v.y;
            qv[4 * i + 2] = v.z; qv[4 * i + 3] = v.w;
        }
        float bv = -3.0e38f;
        int bi = 0x7fffffff;
        if (c > CAP) {  // overflow fallback: exact full scan (should be ~never)
            for (int id = 0; id < NCODE; ++id) {
                float s = exact_score(qv, ew, id);
                if (s > bv) { bv = s; bi = id; }
            }
        } else {
            for (int k = 0; k < c; ++k) {
                int id = cidx[q * CAP + k];
                float s = exact_score(qv, ew, id);
                if (s > bv || (s == bv && id < bi)) { bv = s; bi = id; }
            }
        }
        g_ind[n] = bi;
    }
}

// ---------------------------------------------------------------------------
// K3: gather + outputs + loss. Fully coalesced: phase A (e-fast) computes
// loss + z_q_flat and stages rows in smem; phase B writes [B,E,H,W] hw-fast.
// block 256, 64 pixels per block, grid 512.
// ---------------------------------------------------------------------------
__global__ __launch_bounds__(256) void k_gather(const float* __restrict__ ew,
                                                float* __restrict__ out,
                                                int full_out) {
    __shared__ float vt[64][EMB + 1];   // staged codebook rows, 16.6 KB
    int tid = threadIdx.x;
    int blk = blockIdx.x;

    // phase A: e-fast (coalesced reads + z_q_flat writes)
    int e = tid & 63, pg = tid >> 6;
    float s = 0.f;
    for (int pp = pg; pp < 64; pp += 4) {
        int n = blk * 64 + pp;
        int idx = g_ind[n];                       // broadcast within 64-group
        float v = ew[(size_t)idx * EMB + e];      // coalesced row read
        vt[pp][e] = v;
        float d = v - g_ze[(size_t)n * EMB + e];  // coalesced
        s += d * d;
        if (full_out) out[N_PIX * EMB + (size_t)n * EMB + e] = v;  // coalesced
    }
    if (full_out && tid < 64) {
        int n = blk * 64 + tid;
        out[2 * N_PIX * EMB + 1 + n] = (float)g_ind[n];
    }
    __syncthreads();

    // phase B: hw-fast coalesced [B,E,H,W] writes
    int p = tid & 63, eg = tid >> 6;
    int n = blk * 64 + p;
    int b = n >> 10, hw = n & 1023;
    float* outp = out + (size_t)b * (EMB * HW) + hw;
#pragma unroll
    for (int ee = 0; ee < EMB / 4; ++ee)
        outp[(size_t)(eg + 4 * ee) * HW] = vt[p][eg + 4 * ee];

    // loss reduce
#pragma unroll
    for (int off = 16; off > 0; off >>= 1)
        s += __shfl_down_sync(0xffffffffu, s, off);
    __shared__ float ps[8];
    if ((tid & 31) == 0) ps[tid >> 5] = s;
    __syncthreads();
    if (tid < 8) {
        s = ps[tid];
#pragma unroll
        for (int off = 4; off > 0; off >>= 1)
            s += __shfl_down_sync(0xffu, s, off);
        if (tid == 0) atomicAdd(&g_loss, s);
    }
}

__global__ void k_fin(float* __restrict__ out, int full_out) {
    if (full_out)
        out[2 * N_PIX * EMB] = 12.5f * g_loss / (float)(N_PIX * EMB);
}

// ---------------------------------------------------------------------------
extern "C" void kernel_launch(void* const* d_in, const int* in_sizes, int n_in,
                              void* d_out, int out_size) {
    const float* z  = (const float*)d_in[0];
    const float* pw = (const float*)d_in[1];
    const float* pb = (const float*)d_in[2];
    const float* ew = (const float*)d_in[3];
    float* out = (float*)d_out;

    int full_out = (out_size >= 2 * N_PIX * EMB + 1 + N_PIX) ? 1 : 0;

    cudaFuncSetAttribute(k_argmax_mma, cudaFuncAttributeMaxDynamicSharedMemorySize,
                         SMEM_TOTAL);

    k_wn<<<NCODE / 256, 256>>>(ew);
    k_proj<<<N_PIX / 16, 256>>>(z, pw, pb);
    k_argmax_mma<<<N_PIX / 128, 256, SMEM_TOTAL>>>(ew);
    k_gather<<<N_PIX / 64, 256>>>(ew, out, full_out);
    k_fin<<<1, 1>>>(out, full_out);
}